// round 6
// baseline (speedup 1.0000x reference)
#include <cuda_runtime.h>

#define CUT2 25.0f
#define IT 4            // i-rows per group (register tile)
#define NROWS_CAP 65536
#define NGRP_CAP  (NROWS_CAP / IT)
#define MAXCH 40        // max 32-wide j-chunks per row (nat <= 1280)
#define NSYS_CAP 2048

// Scratch (static __device__, allocation-free).
__device__ uint4 g_mask[NGRP_CAP * MAXCH];  // [group][chunk] -> 4 rows' ballots
__device__ int   g_offsets[NROWS_CAP];      // within-system exclusive prefix
__device__ int   g_systot[NSYS_CAP];        // per-system totals

// ---- bit-exact reference arithmetic (DO NOT CHANGE) ----
__device__ __forceinline__ float sqnorm3(float x, float y, float z) {
    return __fadd_rn(__fadd_rn(__fmul_rn(x, x), __fmul_rn(y, y)), __fmul_rn(z, z));
}
// gram dot via GEMM-style FMA chain: c = rn(x*x'); c = fma(y,y',c); c = fma(z,z',c)
__device__ __forceinline__ float dot3(float4 a, float4 b) {
    return __fmaf_rn(a.z, b.z, __fmaf_rn(a.y, b.y, __fmul_rn(a.x, b.x)));
}
__device__ __forceinline__ float d12_of(float4 ai, float4 aj) {
    return __fsub_rn(__fadd_rn(ai.w, aj.w), __fmul_rn(2.0f, dot3(ai, aj)));
}
// --------------------------------------------------------

extern __shared__ float4 s_at[];  // nch*32 entries: (x,y,z,sq); tail = sentinel

// K1: mask sweep. Warp handles IT consecutive rows; per 32-j chunk it emits
// one uint4 of ballots (bit set <=> pair (i, j) is a hit, j > i). No hit data
// is materialized — j and d12 are reconstructed later from the bit position.
__global__ void sweep_kernel(const float* __restrict__ coords, int nat,
                             int nch, int ngroups) {
    int s = blockIdx.x;
    {
        const float* base = coords + (size_t)s * nat * 3;
        int P = nch * 32;
        for (int t = threadIdx.x; t < P; t += blockDim.x) {
            if (t < nat) {
                float x = base[3 * t + 0];
                float y = base[3 * t + 1];
                float z = base[3 * t + 2];
                s_at[t] = make_float4(x, y, z, sqnorm3(x, y, z));
            } else {
                s_at[t] = make_float4(0.f, 0.f, 0.f, 1e30f);  // never a hit
            }
        }
        __syncthreads();
    }

    int lane = threadIdx.x & 31;
    int wid  = (threadIdx.x >> 5) + blockIdx.y * (blockDim.x >> 5);
    int wtot = (blockDim.x >> 5) * gridDim.y;

    // Zigzag group assignment: base 0 -> g = wid, base 1 -> g = 2*wtot-1-wid,
    // ... pairs high-cost with low-cost groups (triangular work) per warp.
    for (int base = 0; base * wtot < ngroups; base++) {
        int g = (base & 1) ? ((base + 1) * wtot - 1 - wid) : (base * wtot + wid);
        if (g >= ngroups) continue;

        int r0 = g * IT;
        float4 a[IT];
#pragma unroll
        for (int t = 0; t < IT; t++) {
            int i = r0 + t;
            a[t] = (i < nat) ? s_at[i] : make_float4(0.f, 0.f, 0.f, 1e30f);
        }

        uint4* mp = &g_mask[(size_t)(s * ngroups + g) * nch];
        int c0 = (r0 + 1) >> 5;  // first chunk containing any j > r0

        // Peeled first chunk: needs the j > i predicate.
        int c = c0;
        if (c < nch) {
            int j = (c << 5) + lane;
            float4 aj = s_at[j];
            unsigned m0, m1, m2, m3;
            {
                float d = d12_of(a[0], aj);
                m0 = __ballot_sync(0xffffffffu, (d < CUT2) && (j > r0));
            }
            {
                float d = d12_of(a[1], aj);
                m1 = __ballot_sync(0xffffffffu, (d < CUT2) && (j > r0 + 1));
            }
            {
                float d = d12_of(a[2], aj);
                m2 = __ballot_sync(0xffffffffu, (d < CUT2) && (j > r0 + 2));
            }
            {
                float d = d12_of(a[3], aj);
                m3 = __ballot_sync(0xffffffffu, (d < CUT2) && (j > r0 + 3));
            }
            if (lane == 0) mp[c] = make_uint4(m0, m1, m2, m3);
            c++;
        }

        // Clean chunks: j > i guaranteed; sentinels kill j >= nat.
        for (; c < nch; c++) {
            int j = (c << 5) + lane;
            float4 aj = s_at[j];
            unsigned m0, m1, m2, m3;
            m0 = __ballot_sync(0xffffffffu, d12_of(a[0], aj) < CUT2);
            m1 = __ballot_sync(0xffffffffu, d12_of(a[1], aj) < CUT2);
            m2 = __ballot_sync(0xffffffffu, d12_of(a[2], aj) < CUT2);
            m3 = __ballot_sync(0xffffffffu, d12_of(a[3], aj) < CUT2);
            if (lane == 0) mp[c] = make_uint4(m0, m1, m2, m3);
        }
    }
}

// K2: per-system exclusive scan; counts derived from the masks directly.
// grid = nsys, block = 1024 (requires nat <= 1024).
__global__ void scan_sys_kernel(int nat, int nch, int ngroups) {
    __shared__ int wsum[32];
    int s = blockIdx.x;
    int tid = threadIdx.x;
    int lane = tid & 31, w = tid >> 5;

    int v = 0;
    if (tid < nat) {
        int g = tid >> 2, t = tid & 3;
        int c0 = ((g << 2) + 1) >> 5;
        const unsigned* mp =
            (const unsigned*)&g_mask[(size_t)(s * ngroups + g) * nch];
        for (int c = c0; c < nch; c++) v += __popc(mp[(c << 2) + t]);
    }

    int x = v;  // inclusive warp scan
#pragma unroll
    for (int o = 1; o < 32; o <<= 1) {
        int u = __shfl_up_sync(0xffffffffu, x, o);
        if (lane >= o) x += u;
    }
    if (lane == 31) wsum[w] = x;
    __syncthreads();
    if (w == 0) {
        int y = wsum[lane];
#pragma unroll
        for (int o = 1; o < 32; o <<= 1) {
            int u = __shfl_up_sync(0xffffffffu, y, o);
            if (lane >= o) y += u;
        }
        wsum[lane] = y;
    }
    __syncthreads();
    int incl = x + ((w > 0) ? wsum[w - 1] : 0);
    if (tid < nat) g_offsets[s * nat + tid] = incl - v;
    if (tid == nat - 1) g_systot[s] = incl;
}

// K3: fused output. Blocks [0, WB): one warp per row; lane c owns chunk c,
// shfl-scan of popcounts gives each hit its exact j-ascending position; d12 is
// recomputed bit-exactly from coords. Blocks [WB, ...): padding region.
// Output float32 layout (maxp = MAX_PAIRS):
//   [0,M): src   [M,2M): dst    (edge_src = concat(src,dst))
//   [2M,3M): dst [3M,4M): src   (edge_dst = concat(dst,src))
//   [4M,5M): d12 [5M,6M): d12   [6M]: npairs
__global__ void output_kernel(const float* __restrict__ coords,
                              float* __restrict__ out, int maxp, int nrows,
                              int nat, int nsys, int nch, int ngroups, int WB,
                              float padval, int vec_ok) {
    __shared__ int s_sysoff[NSYS_CAP + 1];
    int tid = threadIdx.x;
    if (tid < 32) {
        int per = (nsys + 31) >> 5;
        int base = tid * per;
        int loc[8];
        int sum = 0;
        for (int u = 0; u < per && u < 8; u++) {
            int idx = base + u;
            int t = (idx < nsys) ? g_systot[idx] : 0;
            loc[u] = sum;
            sum += t;
        }
        int x = sum;
#pragma unroll
        for (int o = 1; o < 32; o <<= 1) {
            int uu = __shfl_up_sync(0xffffffffu, x, o);
            if (tid >= o) x += uu;
        }
        int excl = x - sum;
        for (int u = 0; u < per && u < 8; u++) {
            int idx = base + u;
            if (idx < nsys) s_sysoff[idx] = excl + loc[u];
        }
        if (tid == 31) s_sysoff[nsys] = x;  // grand total = npairs
    }
    __syncthreads();
    int np = s_sysoff[nsys];

    if (blockIdx.x < WB) {
        int row = blockIdx.x * (blockDim.x >> 5) + (tid >> 5);
        if (row >= nrows) return;
        int lane = tid & 31;
        int s = row / nat, i = row - s * nat;
        int g = i >> 2, t = i & 3;
        int c0 = ((g << 2) + 1) >> 5;

        unsigned m = 0;
        if (lane >= c0 && lane < nch)
            m = ((const unsigned*)&g_mask[(size_t)(s * ngroups + g) * nch])
                 [(lane << 2) + t];
        int cnt = __popc(m);

        int x = cnt;  // inclusive scan across lanes (chunks)
#pragma unroll
        for (int o = 1; o < 32; o <<= 1) {
            int u = __shfl_up_sync(0xffffffffu, x, o);
            if (lane >= o) x += u;
        }
        int mybase = x - cnt;

        if (m) {
            const float* ci = coords + (size_t)row * 3;
            float xi = ci[0], yi = ci[1], zi = ci[2];
            float4 ai = make_float4(xi, yi, zi, sqnorm3(xi, yi, zi));
            float fsrc = (float)row;
            int off = s_sysoff[s] + g_offsets[row] + mybase;

            int r = 0;
            while (m) {
                int b = __ffs(m) - 1;
                m &= m - 1;
                int j = (lane << 5) + b;
                int gj = s * nat + j;
                const float* cj = coords + (size_t)gj * 3;
                float xj = cj[0], yj = cj[1], zj = cj[2];
                float4 aj = make_float4(xj, yj, zj, sqnorm3(xj, yj, zj));
                float d = d12_of(ai, aj);
                int pos = off + r;
                r++;
                if (pos < maxp) {
                    float fdst = (float)gj;
                    out[pos]            = fsrc;
                    out[maxp + pos]     = fdst;
                    out[2 * maxp + pos] = fdst;
                    out[3 * maxp + pos] = fsrc;
                    out[4 * maxp + pos] = d;
                    out[5 * maxp + pos] = d;
                }
            }
        }
    } else {
        int pb = blockIdx.x - WB;
        if (pb == 0 && tid == 0) out[6 * maxp] = (float)np;
        int k0 = (pb * blockDim.x + tid) * 4;
        if (k0 >= maxp) return;
        if (k0 >= np && k0 + 3 < maxp && vec_ok) {
            float4 pv = make_float4(padval, padval, padval, padval);
            float4 cv = make_float4(CUT2, CUT2, CUT2, CUT2);
            *(float4*)(out + k0)            = pv;
            *(float4*)(out + maxp + k0)     = pv;
            *(float4*)(out + 2 * maxp + k0) = pv;
            *(float4*)(out + 3 * maxp + k0) = pv;
            *(float4*)(out + 4 * maxp + k0) = cv;
            *(float4*)(out + 5 * maxp + k0) = cv;
        } else {
#pragma unroll
            for (int u = 0; u < 4; u++) {
                int k = k0 + u;
                if (k < maxp && k >= np) {
                    out[k]            = padval;
                    out[maxp + k]     = padval;
                    out[2 * maxp + k] = padval;
                    out[3 * maxp + k] = padval;
                    out[4 * maxp + k] = CUT2;
                    out[5 * maxp + k] = CUT2;
                }
            }
        }
    }
}

extern "C" void kernel_launch(void* const* d_in, const int* in_sizes, int n_in,
                              void* d_out, int out_size) {
    const float* coords = (const float*)d_in[0];
    int n    = in_sizes[1];          // total atoms
    int nsys = in_sizes[2];          // systems
    int nat  = n / nsys;
    int maxp = (out_size - 1) / 6;   // MAX_PAIRS
    float* out = (float*)d_out;

    int nch = (nat + 31) >> 5;            // 32-wide j-chunks per row
    int ngroups = (nat + IT - 1) / IT;
    size_t smem = (size_t)nch * 32 * sizeof(float4);
    int vec_ok = ((maxp & 3) == 0) ? 1 : 0;

    int WB = (n + 7) / 8;                          // write blocks (8 warps ea)
    int PB = (maxp + 256 * 4 - 1) / (256 * 4);     // pad blocks

    sweep_kernel<<<dim3(nsys, 11), 256, smem>>>(coords, nat, nch, ngroups);
    scan_sys_kernel<<<nsys, 1024>>>(nat, nch, ngroups);
    output_kernel<<<WB + PB, 256>>>(coords, out, maxp, n, nat, nsys, nch,
                                    ngroups, WB, (float)n, vec_ok);
}